// round 12
// baseline (speedup 1.0000x reference)
#include <cuda_runtime.h>
#include <cuda_fp16.h>
#include <cstdint>

#define MAX_N 50048
#define MAX_E 800000
#define HID 128
#define NG 64

// ---------------- scratch (device globals; no allocation allowed) ------------
__device__ __half2 g_hh[(size_t)MAX_N * 64];
__device__ float g_Wcomb[HID * HID];
__device__ float g_bcomb[HID];
__device__ float g_esrc[MAX_N * 4];
__device__ float g_edst[MAX_N * 4];
__device__ int   g_deg[MAX_N];
__device__ int   g_off[MAX_N + 1];
__device__ int   g_cursor[MAX_N];
__device__ int   g_srcsort[MAX_E];
__device__ int   g_flag[64];
__device__ int   g_agg[64];
__device__ float g_pooled[NG * HID];

// ---------------- helpers ----------------------------------------------------
__device__ __forceinline__ unsigned long long pk2(float lo, float hi) {
    unsigned long long r;
    asm("mov.b64 %0, {%1,%2};" : "=l"(r) : "f"(lo), "f"(hi));
    return r;
}
__device__ __forceinline__ void fma2(unsigned long long& d, unsigned long long a,
                                     unsigned long long b) {
    asm("fma.rn.f32x2 %0, %1, %2, %0;" : "+l"(d) : "l"(a), "l"(b));
}
__device__ __forceinline__ float2 upk(unsigned long long v) {
    float2 r;
    asm("mov.b64 {%0,%1}, %2;" : "=f"(r.x), "=f"(r.y) : "l"(v));
    return r;
}
__device__ __forceinline__ void red_add_v4(float* addr, float4 v) {
    asm volatile("red.global.add.v4.f32 [%0], {%1,%2,%3,%4};"
                 :: "l"(addr), "f"(v.x), "f"(v.y), "f"(v.z), "f"(v.w) : "memory");
}
__device__ __forceinline__ float lrelu(float x) { return x > 0.f ? x : 0.2f * x; }

// ---------------- fused preamble: init (blocks<nbI) + Wcomb/bias (rest) -------
__global__ __launch_bounds__(256) void init_wcomb(int* __restrict__ deg,
                                                  float* __restrict__ pooled,
                                                  int* __restrict__ flags,
                                                  const float* __restrict__ Wp,
                                                  const float* __restrict__ Wg,
                                                  const float* __restrict__ bp,
                                                  float* __restrict__ Wc,
                                                  float* __restrict__ bc,
                                                  int N, int nbI) {
    int b = blockIdx.x;
    if (b < nbI) {
        int i = b * 256 + threadIdx.x;
        if (i < N) deg[i] = 0;
        if (i < NG * HID) pooled[i] = 0.f;
        if (i < 64) flags[i] = 0;
    } else if (b < nbI + 64) {
        int idx = (b - nbI) * 256 + threadIdx.x;
        int r = idx >> 7, c = idx & 127;
        float s0 = 0.f, s1 = 0.f, s2 = 0.f, s3 = 0.f;
#pragma unroll 4
        for (int k = 0; k < 128; k += 4) {
            s0 += Wp[r * 128 + k + 0] * Wg[(k + 0) * 128 + c];
            s1 += Wp[r * 128 + k + 1] * Wg[(k + 1) * 128 + c];
            s2 += Wp[r * 128 + k + 2] * Wg[(k + 2) * 128 + c];
            s3 += Wp[r * 128 + k + 3] * Wg[(k + 3) * 128 + c];
        }
        Wc[idx] = (s0 + s1) + (s2 + s3);
    } else if (threadIdx.x < 128) {
        int c = threadIdx.x;
        float s = 0.f;
#pragma unroll 8
        for (int k = 0; k < 128; k++) s += bp[k] * Wg[k * 128 + c];
        bc[c] = s;
    }
}

// ---------------- GEMM half2 out + fused attention coefficients ---------------
#define AT_LD 132
__global__ __launch_bounds__(256, 2) void gemm128h(const float* __restrict__ A,
                                                   const float* __restrict__ W,
                                                   const float* __restrict__ bias,
                                                   const float* __restrict__ a_src,
                                                   const float* __restrict__ a_dst,
                                                   __half2* __restrict__ C,
                                                   float* __restrict__ esrc,
                                                   float* __restrict__ edst, int N) {
    extern __shared__ float sm[];
    float* Ws = sm;                 // 128*128
    float* At = sm + 16384;         // 64*AT_LD
    const int t = threadIdx.x;
    const int row0 = blockIdx.x * 128;

    const float4* Wg = (const float4*)W;
    float4* Wsv = (float4*)Ws;
#pragma unroll
    for (int i = 0; i < 16; i++) Wsv[t + i * 256] = Wg[t + i * 256];

    const int w = t >> 5, lane = t & 31;
    const int rowb = (w >> 1) * 32;
    const int colb = (w & 1) * 64;
    const int rg = lane >> 3, cg = lane & 7;
    const int r8 = rowb + rg * 8;
    const int c8 = colb + cg * 8;

    unsigned long long acc[4][8];
#pragma unroll
    for (int i = 0; i < 4; i++)
#pragma unroll
        for (int j = 0; j < 8; j++) acc[i][j] = 0ull;

#pragma unroll
    for (int half = 0; half < 2; half++) {
        __syncthreads();
#pragma unroll
        for (int i = 0; i < 8; i++) {
            int idx = t + i * 256;
            int r  = idx >> 4;
            int k4 = idx & 15;
            float4 v = make_float4(0.f, 0.f, 0.f, 0.f);
            if (row0 + r < N)
                v = *(const float4*)(A + (size_t)(row0 + r) * 128 + half * 64 + k4 * 4);
            At[(k4 * 4 + 0) * AT_LD + r] = v.x;
            At[(k4 * 4 + 1) * AT_LD + r] = v.y;
            At[(k4 * 4 + 2) * AT_LD + r] = v.z;
            At[(k4 * 4 + 3) * AT_LD + r] = v.w;
        }
        __syncthreads();

#pragma unroll 4
        for (int k = 0; k < 64; k++) {
            ulonglong2 a01 = *(const ulonglong2*)(At + k * AT_LD + r8);
            ulonglong2 a23 = *(const ulonglong2*)(At + k * AT_LD + r8 + 4);
            float4 w0 = *(const float4*)(Ws + (half * 64 + k) * 128 + c8);
            float4 w1 = *(const float4*)(Ws + (half * 64 + k) * 128 + c8 + 4);
            unsigned long long ap[4] = {a01.x, a01.y, a23.x, a23.y};
            unsigned long long wp[8] = {pk2(w0.x, w0.x), pk2(w0.y, w0.y),
                                        pk2(w0.z, w0.z), pk2(w0.w, w0.w),
                                        pk2(w1.x, w1.x), pk2(w1.y, w1.y),
                                        pk2(w1.z, w1.z), pk2(w1.w, w1.w)};
#pragma unroll
            for (int i = 0; i < 4; i++)
#pragma unroll
                for (int j = 0; j < 8; j++) fma2(acc[i][j], ap[i], wp[j]);
        }
    }

    float4 b0 = *(const float4*)(bias + c8);
    float4 b1 = *(const float4*)(bias + c8 + 4);
    float bb[8] = {b0.x, b0.y, b0.z, b0.w, b1.x, b1.y, b1.z, b1.w};
    float4 as0 = *(const float4*)(a_src + c8);
    float4 as1 = *(const float4*)(a_src + c8 + 4);
    float4 ad0 = *(const float4*)(a_dst + c8);
    float4 ad1 = *(const float4*)(a_dst + c8 + 4);
    float sa8[8] = {as0.x, as0.y, as0.z, as0.w, as1.x, as1.y, as1.z, as1.w};
    float sd8[8] = {ad0.x, ad0.y, ad0.z, ad0.w, ad1.x, ad1.y, ad1.z, ad1.w};
    const int head = c8 >> 5;

#pragma unroll
    for (int i = 0; i < 4; i++) {
#pragma unroll
        for (int hr = 0; hr < 2; hr++) {
            int r = r8 + 2 * i + hr;
            bool ok = (row0 + r < N);
            float v[8];
#pragma unroll
            for (int j = 0; j < 8; j++) {
                float2 p = upk(acc[i][j]);
                v[j] = (hr ? p.y : p.x) + bb[j];
            }
            if (ok) {
                __half2 p0 = __float22half2_rn(make_float2(v[0], v[1]));
                __half2 p1 = __float22half2_rn(make_float2(v[2], v[3]));
                __half2 p2 = __float22half2_rn(make_float2(v[4], v[5]));
                __half2 p3 = __float22half2_rn(make_float2(v[6], v[7]));
                uint4 u;
                u.x = *(unsigned*)&p0; u.y = *(unsigned*)&p1;
                u.z = *(unsigned*)&p2; u.w = *(unsigned*)&p3;
                *(uint4*)(C + (size_t)(row0 + r) * 64 + c8 / 2) = u;
            }
            float ps = 0.f, pd = 0.f;
#pragma unroll
            for (int j = 0; j < 8; j++) { ps += v[j] * sa8[j]; pd += v[j] * sd8[j]; }
            ps += __shfl_xor_sync(0xFFFFFFFFu, ps, 1);
            pd += __shfl_xor_sync(0xFFFFFFFFu, pd, 1);
            ps += __shfl_xor_sync(0xFFFFFFFFu, ps, 2);
            pd += __shfl_xor_sync(0xFFFFFFFFu, pd, 2);
            if (ok && (lane & 3) == 0) {
                esrc[(row0 + r) * 4 + head] = ps;
                edst[(row0 + r) * 4 + head] = pd;
            }
        }
    }
}

// ---------------- CSR build ---------------------------------------------------
__global__ void hist_kernel(const int* __restrict__ ei, int* __restrict__ deg, int E) {
    int base = (blockIdx.x * blockDim.x + threadIdx.x) * 16;
    if (base >= E) return;
    if (base + 16 <= E) {
        const int4* p = (const int4*)(ei + E + base);
#pragma unroll
        for (int q = 0; q < 4; q++) {
            int4 d = p[q];
            atomicAdd(deg + d.x, 1);
            atomicAdd(deg + d.y, 1);
            atomicAdd(deg + d.z, 1);
            atomicAdd(deg + d.w, 1);
        }
    } else {
        for (int e = base; e < E; e++) atomicAdd(deg + ei[E + e], 1);
    }
}

// single-pass exclusive scan with decoupled lookback (<=64 blocks, all resident)
__global__ __launch_bounds__(256) void scan_fused(const int* __restrict__ deg,
                                                  int* __restrict__ off,
                                                  int* __restrict__ cursor,
                                                  volatile int* __restrict__ flags,
                                                  int* __restrict__ aggs,
                                                  int N, int E) {
    __shared__ int sc[256];
    __shared__ int s_pred[64];
    __shared__ int s_add;
    int t = threadIdx.x, bid = blockIdx.x;
    int base = bid * 1024 + t * 4;
    int v[4];
#pragma unroll
    for (int j = 0; j < 4; j++) v[j] = (base + j < N) ? deg[base + j] : 0;
    int s = v[0] + v[1] + v[2] + v[3];
    sc[t] = s;
    __syncthreads();
    for (int d = 1; d < 256; d <<= 1) {
        int val = (t >= d) ? sc[t - d] : 0;
        __syncthreads();
        sc[t] += val;
        __syncthreads();
    }
    if (t == 0) {
        aggs[bid] = sc[255];
        __threadfence();
        flags[bid] = 1;
    }
    if (t < 64) {
        int p = 0;
        if (t < bid) {
            while (flags[t] == 0) { }
            p = aggs[t];
        }
        s_pred[t] = p;
    }
    __syncthreads();
    if (t == 0) {
        int a = 0;
#pragma unroll 8
        for (int i = 0; i < 64; i++) a += s_pred[i];
        s_add = a;
    }
    __syncthreads();
    int add = s_add;
    int run = add + ((t == 0) ? 0 : sc[t - 1]);
#pragma unroll
    for (int j = 0; j < 4; j++) {
        if (base + j < N) { off[base + j] = run; cursor[base + j] = run; }
        run += v[j];
    }
    if (bid == 0 && t == 0) off[N] = E;
}

__global__ void scatter_kernel(const int* __restrict__ ei, int* __restrict__ cursor,
                               int* __restrict__ srcs, int E) {
    int base = (blockIdx.x * blockDim.x + threadIdx.x) * 4;
    if (base >= E) return;
    if (base + 4 <= E) {
        int4 s = *(const int4*)(ei + base);
        int4 d = *(const int4*)(ei + E + base);
        int p0 = atomicAdd(cursor + d.x, 1);
        int p1 = atomicAdd(cursor + d.y, 1);
        int p2 = atomicAdd(cursor + d.z, 1);
        int p3 = atomicAdd(cursor + d.w, 1);
        srcs[p0] = s.x;
        srcs[p1] = s.y;
        srcs[p2] = s.z;
        srcs[p3] = s.w;
    } else {
        for (int e = base; e < E; e++) {
            int sv = ei[e];
            int pv = atomicAdd(cursor + ei[E + e], 1);
            srcs[pv] = sv;
        }
    }
}

// ---------------- single-pass softmax-aggregate-pool (warp per dst node) ------
// out = (sum_i ex_i * hh_i) / (sum_i ex_i): normalize AFTER accumulation.
// ex is identical across each 8-lane head group, so dsum needs no reduction.
__global__ __launch_bounds__(256) void agg_fused(const int* __restrict__ off,
                                                 const int* __restrict__ srcs,
                                                 const float* __restrict__ esrc,
                                                 const float* __restrict__ edst,
                                                 const __half2* __restrict__ hh,
                                                 const int* __restrict__ batch,
                                                 float* __restrict__ pooled, int N) {
    int w = (blockIdx.x * blockDim.x + threadIdx.x) >> 5;
    int lane = threadIdx.x & 31;
    if (w >= N) return;
    int g = batch[w];
    int beg = off[w], end = off[w + 1];
    int deg = end - beg;
    if (deg == 0) return;
    int h = lane >> 3;
    float bh = edst[w * 4 + h];
    const __half2* hbase = hh + lane * 2;
    const int* sp = srcs + beg;

    float4 acc0 = make_float4(0.f, 0.f, 0.f, 0.f);
    float4 acc1 = make_float4(0.f, 0.f, 0.f, 0.f);
    float4 acc2 = make_float4(0.f, 0.f, 0.f, 0.f);
    float4 acc3 = make_float4(0.f, 0.f, 0.f, 0.f);
    float ds0 = 0.f, ds1 = 0.f, ds2 = 0.f, ds3 = 0.f;

    int i = 0;
    for (; i + 3 < deg; i += 4) {
        int s0 = sp[i], s1 = sp[i + 1], s2 = sp[i + 2], s3 = sp[i + 3];
        float e0 = esrc[s0 * 4 + h];
        float e1 = esrc[s1 * 4 + h];
        float e2 = esrc[s2 * 4 + h];
        float e3 = esrc[s3 * 4 + h];
        uint2 r0 = *(const uint2*)(hbase + (size_t)s0 * 64);
        uint2 r1 = *(const uint2*)(hbase + (size_t)s1 * 64);
        uint2 r2 = *(const uint2*)(hbase + (size_t)s2 * 64);
        uint2 r3 = *(const uint2*)(hbase + (size_t)s3 * 64);
        float x0 = __expf(lrelu(e0 + bh));
        float x1 = __expf(lrelu(e1 + bh));
        float x2 = __expf(lrelu(e2 + bh));
        float x3 = __expf(lrelu(e3 + bh));
        float2 a0 = __half22float2(*(__half2*)&r0.x), c0 = __half22float2(*(__half2*)&r0.y);
        float2 a1 = __half22float2(*(__half2*)&r1.x), c1 = __half22float2(*(__half2*)&r1.y);
        float2 a2 = __half22float2(*(__half2*)&r2.x), c2 = __half22float2(*(__half2*)&r2.y);
        float2 a3 = __half22float2(*(__half2*)&r3.x), c3 = __half22float2(*(__half2*)&r3.y);
        acc0.x += x0 * a0.x; acc0.y += x0 * a0.y; acc0.z += x0 * c0.x; acc0.w += x0 * c0.y;
        acc1.x += x1 * a1.x; acc1.y += x1 * a1.y; acc1.z += x1 * c1.x; acc1.w += x1 * c1.y;
        acc2.x += x2 * a2.x; acc2.y += x2 * a2.y; acc2.z += x2 * c2.x; acc2.w += x2 * c2.y;
        acc3.x += x3 * a3.x; acc3.y += x3 * a3.y; acc3.z += x3 * c3.x; acc3.w += x3 * c3.y;
        ds0 += x0; ds1 += x1; ds2 += x2; ds3 += x3;
    }
    for (; i < deg; i++) {
        int s = sp[i];
        float x = __expf(lrelu(esrc[s * 4 + h] + bh));
        uint2 r = *(const uint2*)(hbase + (size_t)s * 64);
        float2 v0 = __half22float2(*(__half2*)&r.x);
        float2 v1 = __half22float2(*(__half2*)&r.y);
        acc0.x += x * v0.x; acc0.y += x * v0.y;
        acc0.z += x * v1.x; acc0.w += x * v1.y;
        ds0 += x;
    }

    float inv = 1.0f / ((ds0 + ds1) + (ds2 + ds3));
    red_add_v4(pooled + g * 128 + lane * 4,
               make_float4((acc0.x + acc1.x + acc2.x + acc3.x) * inv,
                           (acc0.y + acc1.y + acc2.y + acc3.y) * inv,
                           (acc0.z + acc1.z + acc2.z + acc3.z) * inv,
                           (acc0.w + acc1.w + acc2.w + acc3.w) * inv));
}

// ---------------- classifier: warp per graph; counts via bsearch on batch -----
__global__ __launch_bounds__(1024) void classifier(const float* __restrict__ pooled,
                                                   const int* __restrict__ batch,
                                                   const float* __restrict__ Wc1,
                                                   const float* __restrict__ bc1,
                                                   const float* __restrict__ Wc2,
                                                   const float* __restrict__ bc2,
                                                   float* __restrict__ outp, int N) {
    __shared__ float sW1[128 * 64];
    __shared__ float srow[32][128];
    int t = threadIdx.x;
    int warp = t >> 5, lane = t & 31;
    int g = blockIdx.x * 32 + warp;
    for (int i = t; i < 8192; i += 1024) sW1[i] = Wc1[i];

    int cnt;
    if (lane == 0) {
        int lo = 0, hi = N;
        while (lo < hi) { int m = (lo + hi) >> 1; if (batch[m] < g) lo = m + 1; else hi = m; }
        int lb = lo;
        lo = 0; hi = N;
        while (lo < hi) { int m = (lo + hi) >> 1; if (batch[m] < g + 1) lo = m + 1; else hi = m; }
        cnt = lo - lb;
    }
    cnt = __shfl_sync(0xFFFFFFFFu, cnt, 0);
    float inv = 1.0f / fmaxf((float)cnt, 1.0f);

    float4 rv = *(const float4*)(pooled + g * 128 + lane * 4);
    srow[warp][lane * 4 + 0] = rv.x * inv;
    srow[warp][lane * 4 + 1] = rv.y * inv;
    srow[warp][lane * 4 + 2] = rv.z * inv;
    srow[warp][lane * 4 + 3] = rv.w * inv;
    __syncthreads();

    int j0 = lane * 2;
    float s0 = bc1[j0], s1 = bc1[j0 + 1];
#pragma unroll 8
    for (int k = 0; k < 128; k++) {
        float r = srow[warp][k];
        s0 += r * sW1[k * 64 + j0];
        s1 += r * sW1[k * 64 + j0 + 1];
    }
    s0 = fmaxf(s0, 0.f);
    s1 = fmaxf(s1, 0.f);
    float o0 = s0 * Wc2[j0 * 2]     + s1 * Wc2[(j0 + 1) * 2];
    float o1 = s0 * Wc2[j0 * 2 + 1] + s1 * Wc2[(j0 + 1) * 2 + 1];
#pragma unroll
    for (int d = 16; d; d >>= 1) {
        o0 += __shfl_xor_sync(0xFFFFFFFFu, o0, d);
        o1 += __shfl_xor_sync(0xFFFFFFFFu, o1, d);
    }
    if (lane == 0) {
        outp[g * 2 + 0] = o0 + bc2[0];
        outp[g * 2 + 1] = o1 + bc2[1];
    }
}

// ---------------- launch ------------------------------------------------------
extern "C" void kernel_launch(void* const* d_in, const int* in_sizes, int n_in,
                              void* d_out, int out_size) {
    const float* x      = (const float*)d_in[0];
    const int*   ei     = (const int*)d_in[1];
    const int*   batch  = (const int*)d_in[2];
    const float* W_proj = (const float*)d_in[3];
    const float* b_proj = (const float*)d_in[4];
    const float* W_gat  = (const float*)d_in[5];
    const float* a_src  = (const float*)d_in[6];
    const float* a_dst  = (const float*)d_in[7];
    const float* Wc1    = (const float*)d_in[8];
    const float* bc1    = (const float*)d_in[9];
    const float* Wc2    = (const float*)d_in[10];
    const float* bc2    = (const float*)d_in[11];

    int N = in_sizes[0] / 128;
    int E = in_sizes[1] / 2;

    __half2* p_hh;
    float *p_Wcomb, *p_bcomb, *p_esrc, *p_edst, *p_pooled;
    int *p_deg, *p_off, *p_cursor, *p_srcs, *p_flag, *p_agg;
    cudaGetSymbolAddress((void**)&p_hh, g_hh);
    cudaGetSymbolAddress((void**)&p_Wcomb, g_Wcomb);
    cudaGetSymbolAddress((void**)&p_bcomb, g_bcomb);
    cudaGetSymbolAddress((void**)&p_esrc, g_esrc);
    cudaGetSymbolAddress((void**)&p_edst, g_edst);
    cudaGetSymbolAddress((void**)&p_deg, g_deg);
    cudaGetSymbolAddress((void**)&p_off, g_off);
    cudaGetSymbolAddress((void**)&p_cursor, g_cursor);
    cudaGetSymbolAddress((void**)&p_srcs, g_srcsort);
    cudaGetSymbolAddress((void**)&p_flag, g_flag);
    cudaGetSymbolAddress((void**)&p_agg, g_agg);
    cudaGetSymbolAddress((void**)&p_pooled, g_pooled);

    const int GEMM_SMEM = (16384 + 64 * AT_LD) * 4;
    cudaFuncSetAttribute(gemm128h, cudaFuncAttributeMaxDynamicSharedMemorySize, GEMM_SMEM);

    cudaStream_t s2;
    cudaEvent_t ev_fork, ev_join;
    cudaStreamCreateWithFlags(&s2, cudaStreamNonBlocking);
    cudaEventCreateWithFlags(&ev_fork, cudaEventDisableTiming);
    cudaEventCreateWithFlags(&ev_join, cudaEventDisableTiming);

    int nb = (N + 1023) / 1024;
    int nbI = (N + 255) / 256;

    // ---- stream 0: fused init + Wcomb/bias, then fork
    init_wcomb<<<nbI + 65, 256>>>(p_deg, p_pooled, p_flag,
                                  W_proj, W_gat, b_proj, p_Wcomb, p_bcomb, N, nbI);
    cudaEventRecord(ev_fork, 0);

    // ---- side stream: CSR build
    cudaStreamWaitEvent(s2, ev_fork, 0);
    hist_kernel<<<(E / 16 + 255) / 256, 256, 0, s2>>>(ei, p_deg, E);
    scan_fused<<<nb, 256, 0, s2>>>(p_deg, p_off, p_cursor, p_flag, p_agg, N, E);
    scatter_kernel<<<(E / 4 + 255) / 256, 256, 0, s2>>>(ei, p_cursor, p_srcs, E);
    cudaEventRecord(ev_join, s2);

    // ---- stream 0: hh GEMM (+fused attention coefs)
    gemm128h<<<(N + 127) / 128, 256, GEMM_SMEM>>>(x, p_Wcomb, p_bcomb, a_src, a_dst,
                                                  p_hh, p_esrc, p_edst, N);

    // ---- join, aggregate, classify
    cudaStreamWaitEvent(0, ev_join, 0);
    agg_fused<<<(N * 32 + 255) / 256, 256>>>(p_off, p_srcs, p_esrc, p_edst,
                                             p_hh, batch, p_pooled, N);
    classifier<<<2, 1024>>>(p_pooled, batch, Wc1, bc1, Wc2, bc2, (float*)d_out, N);
}

// round 13
// speedup vs baseline: 1.2137x; 1.2137x over previous
#include <cuda_runtime.h>
#include <cuda_fp16.h>
#include <cstdint>

#define MAX_N 50048
#define MAX_E 800000
#define HID 128
#define NG 64

// ---------------- scratch (device globals; no allocation allowed) ------------
__device__ __half2 g_hh[(size_t)MAX_N * 64];
__device__ float g_Wcomb[HID * HID];
__device__ float g_bcomb[HID];
__device__ float g_esrc[MAX_N * 4];
__device__ float g_edst[MAX_N * 4];
__device__ int   g_deg[MAX_N];
__device__ int   g_off[MAX_N + 1];
__device__ int   g_cursor[MAX_N];
__device__ int   g_srcsort[MAX_E];
__device__ int   g_flag[64];
__device__ int   g_agg[64];
__device__ float g_pooled[NG * HID];

// ---------------- helpers ----------------------------------------------------
__device__ __forceinline__ unsigned long long pk2(float lo, float hi) {
    unsigned long long r;
    asm("mov.b64 %0, {%1,%2};" : "=l"(r) : "f"(lo), "f"(hi));
    return r;
}
__device__ __forceinline__ void fma2(unsigned long long& d, unsigned long long a,
                                     unsigned long long b) {
    asm("fma.rn.f32x2 %0, %1, %2, %0;" : "+l"(d) : "l"(a), "l"(b));
}
__device__ __forceinline__ float2 upk(unsigned long long v) {
    float2 r;
    asm("mov.b64 {%0,%1}, %2;" : "=f"(r.x), "=f"(r.y) : "l"(v));
    return r;
}
__device__ __forceinline__ void red_add_v4(float* addr, float4 v) {
    asm volatile("red.global.add.v4.f32 [%0], {%1,%2,%3,%4};"
                 :: "l"(addr), "f"(v.x), "f"(v.y), "f"(v.z), "f"(v.w) : "memory");
}
__device__ __forceinline__ float lrelu(float x) { return x > 0.f ? x : 0.2f * x; }

// ---------------- fused preamble: init (blocks<nbI) + Wcomb/bias (rest) -------
__global__ __launch_bounds__(256) void init_wcomb(int* __restrict__ deg,
                                                  float* __restrict__ pooled,
                                                  int* __restrict__ flags,
                                                  const float* __restrict__ Wp,
                                                  const float* __restrict__ Wg,
                                                  const float* __restrict__ bp,
                                                  float* __restrict__ Wc,
                                                  float* __restrict__ bc,
                                                  int N, int nbI) {
    int b = blockIdx.x;
    if (b < nbI) {
        int i = b * 256 + threadIdx.x;
        if (i < N) deg[i] = 0;
        if (i < NG * HID) pooled[i] = 0.f;
        if (i < 64) flags[i] = 0;
    } else if (b < nbI + 64) {
        int idx = (b - nbI) * 256 + threadIdx.x;
        int r = idx >> 7, c = idx & 127;
        float s0 = 0.f, s1 = 0.f, s2 = 0.f, s3 = 0.f;
#pragma unroll 4
        for (int k = 0; k < 128; k += 4) {
            s0 += Wp[r * 128 + k + 0] * Wg[(k + 0) * 128 + c];
            s1 += Wp[r * 128 + k + 1] * Wg[(k + 1) * 128 + c];
            s2 += Wp[r * 128 + k + 2] * Wg[(k + 2) * 128 + c];
            s3 += Wp[r * 128 + k + 3] * Wg[(k + 3) * 128 + c];
        }
        Wc[idx] = (s0 + s1) + (s2 + s3);
    } else if (threadIdx.x < 128) {
        int c = threadIdx.x;
        float s = 0.f;
#pragma unroll 8
        for (int k = 0; k < 128; k++) s += bp[k] * Wg[k * 128 + c];
        bc[c] = s;
    }
}

// ---------------- GEMM half2 out + fused attention coefficients ---------------
#define AT_LD 132
__global__ __launch_bounds__(256, 2) void gemm128h(const float* __restrict__ A,
                                                   const float* __restrict__ W,
                                                   const float* __restrict__ bias,
                                                   const float* __restrict__ a_src,
                                                   const float* __restrict__ a_dst,
                                                   __half2* __restrict__ C,
                                                   float* __restrict__ esrc,
                                                   float* __restrict__ edst, int N) {
    extern __shared__ float sm[];
    float* Ws = sm;                 // 128*128
    float* At = sm + 16384;         // 64*AT_LD
    const int t = threadIdx.x;
    const int row0 = blockIdx.x * 128;

    const float4* Wg = (const float4*)W;
    float4* Wsv = (float4*)Ws;
#pragma unroll
    for (int i = 0; i < 16; i++) Wsv[t + i * 256] = Wg[t + i * 256];

    const int w = t >> 5, lane = t & 31;
    const int rowb = (w >> 1) * 32;
    const int colb = (w & 1) * 64;
    const int rg = lane >> 3, cg = lane & 7;
    const int r8 = rowb + rg * 8;
    const int c8 = colb + cg * 8;

    unsigned long long acc[4][8];
#pragma unroll
    for (int i = 0; i < 4; i++)
#pragma unroll
        for (int j = 0; j < 8; j++) acc[i][j] = 0ull;

#pragma unroll
    for (int half = 0; half < 2; half++) {
        __syncthreads();
#pragma unroll
        for (int i = 0; i < 8; i++) {
            int idx = t + i * 256;
            int r  = idx >> 4;
            int k4 = idx & 15;
            float4 v = make_float4(0.f, 0.f, 0.f, 0.f);
            if (row0 + r < N)
                v = *(const float4*)(A + (size_t)(row0 + r) * 128 + half * 64 + k4 * 4);
            At[(k4 * 4 + 0) * AT_LD + r] = v.x;
            At[(k4 * 4 + 1) * AT_LD + r] = v.y;
            At[(k4 * 4 + 2) * AT_LD + r] = v.z;
            At[(k4 * 4 + 3) * AT_LD + r] = v.w;
        }
        __syncthreads();

#pragma unroll 4
        for (int k = 0; k < 64; k++) {
            ulonglong2 a01 = *(const ulonglong2*)(At + k * AT_LD + r8);
            ulonglong2 a23 = *(const ulonglong2*)(At + k * AT_LD + r8 + 4);
            float4 w0 = *(const float4*)(Ws + (half * 64 + k) * 128 + c8);
            float4 w1 = *(const float4*)(Ws + (half * 64 + k) * 128 + c8 + 4);
            unsigned long long ap[4] = {a01.x, a01.y, a23.x, a23.y};
            unsigned long long wp[8] = {pk2(w0.x, w0.x), pk2(w0.y, w0.y),
                                        pk2(w0.z, w0.z), pk2(w0.w, w0.w),
                                        pk2(w1.x, w1.x), pk2(w1.y, w1.y),
                                        pk2(w1.z, w1.z), pk2(w1.w, w1.w)};
#pragma unroll
            for (int i = 0; i < 4; i++)
#pragma unroll
                for (int j = 0; j < 8; j++) fma2(acc[i][j], ap[i], wp[j]);
        }
    }

    float4 b0 = *(const float4*)(bias + c8);
    float4 b1 = *(const float4*)(bias + c8 + 4);
    float bb[8] = {b0.x, b0.y, b0.z, b0.w, b1.x, b1.y, b1.z, b1.w};
    float4 as0 = *(const float4*)(a_src + c8);
    float4 as1 = *(const float4*)(a_src + c8 + 4);
    float4 ad0 = *(const float4*)(a_dst + c8);
    float4 ad1 = *(const float4*)(a_dst + c8 + 4);
    float sa8[8] = {as0.x, as0.y, as0.z, as0.w, as1.x, as1.y, as1.z, as1.w};
    float sd8[8] = {ad0.x, ad0.y, ad0.z, ad0.w, ad1.x, ad1.y, ad1.z, ad1.w};
    const int head = c8 >> 5;

#pragma unroll
    for (int i = 0; i < 4; i++) {
#pragma unroll
        for (int hr = 0; hr < 2; hr++) {
            int r = r8 + 2 * i + hr;
            bool ok = (row0 + r < N);
            float v[8];
#pragma unroll
            for (int j = 0; j < 8; j++) {
                float2 p = upk(acc[i][j]);
                v[j] = (hr ? p.y : p.x) + bb[j];
            }
            if (ok) {
                __half2 p0 = __float22half2_rn(make_float2(v[0], v[1]));
                __half2 p1 = __float22half2_rn(make_float2(v[2], v[3]));
                __half2 p2 = __float22half2_rn(make_float2(v[4], v[5]));
                __half2 p3 = __float22half2_rn(make_float2(v[6], v[7]));
                uint4 u;
                u.x = *(unsigned*)&p0; u.y = *(unsigned*)&p1;
                u.z = *(unsigned*)&p2; u.w = *(unsigned*)&p3;
                *(uint4*)(C + (size_t)(row0 + r) * 64 + c8 / 2) = u;
            }
            float ps = 0.f, pd = 0.f;
#pragma unroll
            for (int j = 0; j < 8; j++) { ps += v[j] * sa8[j]; pd += v[j] * sd8[j]; }
            ps += __shfl_xor_sync(0xFFFFFFFFu, ps, 1);
            pd += __shfl_xor_sync(0xFFFFFFFFu, pd, 1);
            ps += __shfl_xor_sync(0xFFFFFFFFu, ps, 2);
            pd += __shfl_xor_sync(0xFFFFFFFFu, pd, 2);
            if (ok && (lane & 3) == 0) {
                esrc[(row0 + r) * 4 + head] = ps;
                edst[(row0 + r) * 4 + head] = pd;
            }
        }
    }
}

// ---------------- CSR build ---------------------------------------------------
__global__ void hist_kernel(const int* __restrict__ ei, int* __restrict__ deg, int E) {
    int base = (blockIdx.x * blockDim.x + threadIdx.x) * 16;
    if (base >= E) return;
    if (base + 16 <= E) {
        const int4* p = (const int4*)(ei + E + base);
#pragma unroll
        for (int q = 0; q < 4; q++) {
            int4 d = p[q];
            atomicAdd(deg + d.x, 1);
            atomicAdd(deg + d.y, 1);
            atomicAdd(deg + d.z, 1);
            atomicAdd(deg + d.w, 1);
        }
    } else {
        for (int e = base; e < E; e++) atomicAdd(deg + ei[E + e], 1);
    }
}

// single-pass exclusive scan with decoupled lookback (<=64 blocks, all resident)
__global__ __launch_bounds__(256) void scan_fused(const int* __restrict__ deg,
                                                  int* __restrict__ off,
                                                  int* __restrict__ cursor,
                                                  volatile int* __restrict__ flags,
                                                  int* __restrict__ aggs,
                                                  int N, int E) {
    __shared__ int sc[256];
    __shared__ int s_pred[64];
    __shared__ int s_add;
    int t = threadIdx.x, bid = blockIdx.x;
    int base = bid * 1024 + t * 4;
    int v[4];
#pragma unroll
    for (int j = 0; j < 4; j++) v[j] = (base + j < N) ? deg[base + j] : 0;
    int s = v[0] + v[1] + v[2] + v[3];
    sc[t] = s;
    __syncthreads();
    for (int d = 1; d < 256; d <<= 1) {
        int val = (t >= d) ? sc[t - d] : 0;
        __syncthreads();
        sc[t] += val;
        __syncthreads();
    }
    if (t == 0) {
        aggs[bid] = sc[255];
        __threadfence();
        flags[bid] = 1;
    }
    if (t < 64) {
        int p = 0;
        if (t < bid) {
            while (flags[t] == 0) { }
            p = aggs[t];
        }
        s_pred[t] = p;
    }
    __syncthreads();
    if (t == 0) {
        int a = 0;
#pragma unroll 8
        for (int i = 0; i < 64; i++) a += s_pred[i];
        s_add = a;
    }
    __syncthreads();
    int add = s_add;
    int run = add + ((t == 0) ? 0 : sc[t - 1]);
#pragma unroll
    for (int j = 0; j < 4; j++) {
        if (base + j < N) { off[base + j] = run; cursor[base + j] = run; }
        run += v[j];
    }
    if (bid == 0 && t == 0) off[N] = E;
}

__global__ void scatter_kernel(const int* __restrict__ ei, int* __restrict__ cursor,
                               int* __restrict__ srcs, int E) {
    int base = (blockIdx.x * blockDim.x + threadIdx.x) * 4;
    if (base >= E) return;
    if (base + 4 <= E) {
        int4 s = *(const int4*)(ei + base);
        int4 d = *(const int4*)(ei + E + base);
        int p0 = atomicAdd(cursor + d.x, 1);
        int p1 = atomicAdd(cursor + d.y, 1);
        int p2 = atomicAdd(cursor + d.z, 1);
        int p3 = atomicAdd(cursor + d.w, 1);
        srcs[p0] = s.x;
        srcs[p1] = s.y;
        srcs[p2] = s.z;
        srcs[p3] = s.w;
    } else {
        for (int e = base; e < E; e++) {
            int sv = ei[e];
            int pv = atomicAdd(cursor + ei[E + e], 1);
            srcs[pv] = sv;
        }
    }
}

// ---------------- fused softmax + aggregate + pool (warp per dst node) --------
// R10-proven body + block-level pooled reduction (batch is sorted -> most
// blocks are single-graph -> 1 RED per block instead of 8).
#define CAP 64
__global__ __launch_bounds__(256, 6) void agg_fused(const int* __restrict__ off,
                                                    const int* __restrict__ srcs,
                                                    const float* __restrict__ esrc,
                                                    const float* __restrict__ edst,
                                                    const __half2* __restrict__ hh,
                                                    const int* __restrict__ batch,
                                                    float* __restrict__ pooled, int N) {
    __shared__ int    sh_src[8][CAP];
    __shared__ float  sh_al[8][4][CAP + 1];
    __shared__ float4 sacc[8][32];
    __shared__ int    sg[8];
    int wi = threadIdx.x >> 5;
    int w = (blockIdx.x * blockDim.x + threadIdx.x) >> 5;
    int lane = threadIdx.x & 31;

    float4 total = make_float4(0.f, 0.f, 0.f, 0.f);
    int g = -1;

    if (w < N) {
        g = batch[w];
        int beg = off[w], end = off[w + 1];
        int deg = end - beg;
        if (deg > 0) {
            float4 b = *(const float4*)(edst + w * 4);

            // pass A: per-edge exp4 -> transposed smem + denominator reduction
            float4 dsum = make_float4(0.f, 0.f, 0.f, 0.f);
            for (int i = lane; i < deg; i += 32) {
                int s = srcs[beg + i];
                float4 a = *(const float4*)(esrc + s * 4);
                float ex0 = __expf(lrelu(a.x + b.x));
                float ex1 = __expf(lrelu(a.y + b.y));
                float ex2 = __expf(lrelu(a.z + b.z));
                float ex3 = __expf(lrelu(a.w + b.w));
                if (i < CAP) {
                    sh_src[wi][i] = s;
                    sh_al[wi][0][i] = ex0;
                    sh_al[wi][1][i] = ex1;
                    sh_al[wi][2][i] = ex2;
                    sh_al[wi][3][i] = ex3;
                }
                dsum.x += ex0; dsum.y += ex1; dsum.z += ex2; dsum.w += ex3;
            }
#pragma unroll
            for (int d = 16; d; d >>= 1) {
                dsum.x += __shfl_xor_sync(0xFFFFFFFFu, dsum.x, d);
                dsum.y += __shfl_xor_sync(0xFFFFFFFFu, dsum.y, d);
                dsum.z += __shfl_xor_sync(0xFFFFFFFFu, dsum.z, d);
                dsum.w += __shfl_xor_sync(0xFFFFFFFFu, dsum.w, d);
            }
            __syncwarp();

            int h = lane >> 3;
            float bh  = (h == 0) ? b.x : (h == 1) ? b.y : (h == 2) ? b.z : b.w;
            float dh  = (h == 0) ? dsum.x : (h == 1) ? dsum.y : (h == 2) ? dsum.z : dsum.w;
            float inv = 1.0f / dh;

            const float* alp = sh_al[wi][h];
            const int*   sp  = sh_src[wi];
            const __half2* hbase = hh + lane * 2;

            float4 acc0 = make_float4(0.f, 0.f, 0.f, 0.f);
            float4 acc1 = make_float4(0.f, 0.f, 0.f, 0.f);
            int nfast = (deg < CAP) ? deg : CAP;
            int i = 0;
            for (; i + 1 < nfast; i += 2) {
                int s0 = sp[i], s1 = sp[i + 1];
                float al0 = alp[i] * inv, al1 = alp[i + 1] * inv;
                uint2 r0 = *(const uint2*)(hbase + (size_t)s0 * 64);
                uint2 r1 = *(const uint2*)(hbase + (size_t)s1 * 64);
                float2 a0 = __half22float2(*(__half2*)&r0.x);
                float2 b0v = __half22float2(*(__half2*)&r0.y);
                float2 a1 = __half22float2(*(__half2*)&r1.x);
                float2 b1v = __half22float2(*(__half2*)&r1.y);
                acc0.x += al0 * a0.x;  acc0.y += al0 * a0.y;
                acc0.z += al0 * b0v.x; acc0.w += al0 * b0v.y;
                acc1.x += al1 * a1.x;  acc1.y += al1 * a1.y;
                acc1.z += al1 * b1v.x; acc1.w += al1 * b1v.y;
            }
            for (; i < nfast; i++) {
                int s = sp[i];
                float alpha = alp[i] * inv;
                uint2 r = *(const uint2*)(hbase + (size_t)s * 64);
                float2 v0 = __half22float2(*(__half2*)&r.x);
                float2 v1 = __half22float2(*(__half2*)&r.y);
                acc0.x += alpha * v0.x; acc0.y += alpha * v0.y;
                acc0.z += alpha * v1.x; acc0.w += alpha * v1.y;
            }
            for (int j = CAP; j < deg; j++) {  // vanishingly rare overflow path
                int s = srcs[beg + j];
                float alpha = __expf(lrelu(esrc[s * 4 + h] + bh)) * inv;
                uint2 r = *(const uint2*)(hbase + (size_t)s * 64);
                float2 v0 = __half22float2(*(__half2*)&r.x);
                float2 v1 = __half22float2(*(__half2*)&r.y);
                acc0.x += alpha * v0.x; acc0.y += alpha * v0.y;
                acc0.z += alpha * v1.x; acc0.w += alpha * v1.y;
            }
            total = make_float4(acc0.x + acc1.x, acc0.y + acc1.y,
                                acc0.z + acc1.z, acc0.w + acc1.w);
        }
    }

    // block-level reduction by graph id, then one RED per distinct g
    sacc[wi][lane] = total;
    if (lane == 0) sg[wi] = g;
    __syncthreads();
    int myg = sg[wi];
    bool leader = (myg >= 0);
#pragma unroll
    for (int j = 0; j < 8; j++)
        if (j < wi && sg[j] == myg) leader = false;
    if (leader) {
        float4 tot = sacc[wi][lane];
#pragma unroll
        for (int j = 0; j < 8; j++) {
            if (j > wi && sg[j] == myg) {
                float4 o = sacc[j][lane];
                tot.x += o.x; tot.y += o.y; tot.z += o.z; tot.w += o.w;
            }
        }
        red_add_v4(pooled + myg * 128 + lane * 4, tot);
    }
}

// ---------------- classifier: warp per graph; counts via bsearch on batch -----
__global__ __launch_bounds__(1024) void classifier(const float* __restrict__ pooled,
                                                   const int* __restrict__ batch,
                                                   const float* __restrict__ Wc1,
                                                   const float* __restrict__ bc1,
                                                   const float* __restrict__ Wc2,
                                                   const float* __restrict__ bc2,
                                                   float* __restrict__ outp, int N) {
    __shared__ float sW1[128 * 64];
    __shared__ float srow[32][128];
    int t = threadIdx.x;
    int warp = t >> 5, lane = t & 31;
    int g = blockIdx.x * 32 + warp;
    for (int i = t; i < 8192; i += 1024) sW1[i] = Wc1[i];

    int cnt;
    if (lane == 0) {
        int lo = 0, hi = N;
        while (lo < hi) { int m = (lo + hi) >> 1; if (batch[m] < g) lo = m + 1; else hi = m; }
        int lb = lo;
        lo = 0; hi = N;
        while (lo < hi) { int m = (lo + hi) >> 1; if (batch[m] < g + 1) lo = m + 1; else hi = m; }
        cnt = lo - lb;
    }
    cnt = __shfl_sync(0xFFFFFFFFu, cnt, 0);
    float inv = 1.0f / fmaxf((float)cnt, 1.0f);

    float4 rv = *(const float4*)(pooled + g * 128 + lane * 4);
    srow[warp][lane * 4 + 0] = rv.x * inv;
    srow[warp][lane * 4 + 1] = rv.y * inv;
    srow[warp][lane * 4 + 2] = rv.z * inv;
    srow[warp][lane * 4 + 3] = rv.w * inv;
    __syncthreads();

    int j0 = lane * 2;
    float s0 = bc1[j0], s1 = bc1[j0 + 1];
#pragma unroll 8
    for (int k = 0; k < 128; k++) {
        float r = srow[warp][k];
        s0 += r * sW1[k * 64 + j0];
        s1 += r * sW1[k * 64 + j0 + 1];
    }
    s0 = fmaxf(s0, 0.f);
    s1 = fmaxf(s1, 0.f);
    float o0 = s0 * Wc2[j0 * 2]     + s1 * Wc2[(j0 + 1) * 2];
    float o1 = s0 * Wc2[j0 * 2 + 1] + s1 * Wc2[(j0 + 1) * 2 + 1];
#pragma unroll
    for (int d = 16; d; d >>= 1) {
        o0 += __shfl_xor_sync(0xFFFFFFFFu, o0, d);
        o1 += __shfl_xor_sync(0xFFFFFFFFu, o1, d);
    }
    if (lane == 0) {
        outp[g * 2 + 0] = o0 + bc2[0];
        outp[g * 2 + 1] = o1 + bc2[1];
    }
}

// ---------------- launch ------------------------------------------------------
extern "C" void kernel_launch(void* const* d_in, const int* in_sizes, int n_in,
                              void* d_out, int out_size) {
    const float* x      = (const float*)d_in[0];
    const int*   ei     = (const int*)d_in[1];
    const int*   batch  = (const int*)d_in[2];
    const float* W_proj = (const float*)d_in[3];
    const float* b_proj = (const float*)d_in[4];
    const float* W_gat  = (const float*)d_in[5];
    const float* a_src  = (const float*)d_in[6];
    const float* a_dst  = (const float*)d_in[7];
    const float* Wc1    = (const float*)d_in[8];
    const float* bc1    = (const float*)d_in[9];
    const float* Wc2    = (const float*)d_in[10];
    const float* bc2    = (const float*)d_in[11];

    int N = in_sizes[0] / 128;
    int E = in_sizes[1] / 2;

    __half2* p_hh;
    float *p_Wcomb, *p_bcomb, *p_esrc, *p_edst, *p_pooled;
    int *p_deg, *p_off, *p_cursor, *p_srcs, *p_flag, *p_agg;
    cudaGetSymbolAddress((void**)&p_hh, g_hh);
    cudaGetSymbolAddress((void**)&p_Wcomb, g_Wcomb);
    cudaGetSymbolAddress((void**)&p_bcomb, g_bcomb);
    cudaGetSymbolAddress((void**)&p_esrc, g_esrc);
    cudaGetSymbolAddress((void**)&p_edst, g_edst);
    cudaGetSymbolAddress((void**)&p_deg, g_deg);
    cudaGetSymbolAddress((void**)&p_off, g_off);
    cudaGetSymbolAddress((void**)&p_cursor, g_cursor);
    cudaGetSymbolAddress((void**)&p_srcs, g_srcsort);
    cudaGetSymbolAddress((void**)&p_flag, g_flag);
    cudaGetSymbolAddress((void**)&p_agg, g_agg);
    cudaGetSymbolAddress((void**)&p_pooled, g_pooled);

    const int GEMM_SMEM = (16384 + 64 * AT_LD) * 4;
    cudaFuncSetAttribute(gemm128h, cudaFuncAttributeMaxDynamicSharedMemorySize, GEMM_SMEM);

    cudaStream_t s2;
    cudaEvent_t ev_fork, ev_join;
    cudaStreamCreateWithFlags(&s2, cudaStreamNonBlocking);
    cudaEventCreateWithFlags(&ev_fork, cudaEventDisableTiming);
    cudaEventCreateWithFlags(&ev_join, cudaEventDisableTiming);

    int nb = (N + 1023) / 1024;
    int nbI = (N + 255) / 256;

    // ---- stream 0: fused init + Wcomb/bias, then fork
    init_wcomb<<<nbI + 65, 256>>>(p_deg, p_pooled, p_flag,
                                  W_proj, W_gat, b_proj, p_Wcomb, p_bcomb, N, nbI);
    cudaEventRecord(ev_fork, 0);

    // ---- side stream: CSR build
    cudaStreamWaitEvent(s2, ev_fork, 0);
    hist_kernel<<<(E / 16 + 255) / 256, 256, 0, s2>>>(ei, p_deg, E);
    scan_fused<<<nb, 256, 0, s2>>>(p_deg, p_off, p_cursor, p_flag, p_agg, N, E);
    scatter_kernel<<<(E / 4 + 255) / 256, 256, 0, s2>>>(ei, p_cursor, p_srcs, E);
    cudaEventRecord(ev_join, s2);

    // ---- stream 0: hh GEMM (+fused attention coefs)
    gemm128h<<<(N + 127) / 128, 256, GEMM_SMEM>>>(x, p_Wcomb, p_bcomb, a_src, a_dst,
                                                  p_hh, p_esrc, p_edst, N);

    // ---- join, aggregate, classify
    cudaStreamWaitEvent(0, ev_join, 0);
    agg_fused<<<(N * 32 + 255) / 256, 256>>>(p_off, p_srcs, p_esrc, p_edst,
                                             p_hh, batch, p_pooled, N);
    classifier<<<2, 1024>>>(p_pooled, batch, Wc1, bc1, Wc2, bc2, (float*)d_out, N);
}

// round 14
// speedup vs baseline: 1.2413x; 1.0228x over previous
#include <cuda_runtime.h>
#include <cuda_fp16.h>
#include <cstdint>

#define MAX_N 50048
#define MAX_E 800000
#define HID 128
#define NG 64

// ---------------- scratch (device globals; no allocation allowed) ------------
__device__ __half2 g_hh[(size_t)MAX_N * 64];
__device__ float g_Wcomb[HID * HID];
__device__ float g_bcomb[HID];
__device__ float g_esrc[MAX_N * 4];
__device__ float g_edst[MAX_N * 4];
__device__ int   g_deg[MAX_N];
__device__ int   g_off[MAX_N + 1];
__device__ int   g_pos[MAX_E];
__device__ int   g_srcsort[MAX_E];
__device__ int   g_flag[64];
__device__ int   g_agg[64];
__device__ float g_pooled[NG * HID];

// ---------------- helpers ----------------------------------------------------
__device__ __forceinline__ unsigned long long pk2(float lo, float hi) {
    unsigned long long r;
    asm("mov.b64 %0, {%1,%2};" : "=l"(r) : "f"(lo), "f"(hi));
    return r;
}
__device__ __forceinline__ void fma2(unsigned long long& d, unsigned long long a,
                                     unsigned long long b) {
    asm("fma.rn.f32x2 %0, %1, %2, %0;" : "+l"(d) : "l"(a), "l"(b));
}
__device__ __forceinline__ float2 upk(unsigned long long v) {
    float2 r;
    asm("mov.b64 {%0,%1}, %2;" : "=f"(r.x), "=f"(r.y) : "l"(v));
    return r;
}
__device__ __forceinline__ void red_add_v4(float* addr, float4 v) {
    asm volatile("red.global.add.v4.f32 [%0], {%1,%2,%3,%4};"
                 :: "l"(addr), "f"(v.x), "f"(v.y), "f"(v.z), "f"(v.w) : "memory");
}
__device__ __forceinline__ float lrelu(float x) { return x > 0.f ? x : 0.2f * x; }

// ---------------- preamble on stream0: zero pooled/agg + Wcomb/bias -----------
__global__ __launch_bounds__(256) void init_wcomb(float* __restrict__ pooled,
                                                  const float* __restrict__ Wp,
                                                  const float* __restrict__ Wg,
                                                  const float* __restrict__ bp,
                                                  float* __restrict__ Wc,
                                                  float* __restrict__ bc) {
    int b = blockIdx.x;
    if (b < 32) {
        int i = b * 256 + threadIdx.x;
        if (i < NG * HID) pooled[i] = 0.f;
    } else if (b < 96) {
        int idx = (b - 32) * 256 + threadIdx.x;
        int r = idx >> 7, c = idx & 127;
        float s0 = 0.f, s1 = 0.f, s2 = 0.f, s3 = 0.f;
#pragma unroll 4
        for (int k = 0; k < 128; k += 4) {
            s0 += Wp[r * 128 + k + 0] * Wg[(k + 0) * 128 + c];
            s1 += Wp[r * 128 + k + 1] * Wg[(k + 1) * 128 + c];
            s2 += Wp[r * 128 + k + 2] * Wg[(k + 2) * 128 + c];
            s3 += Wp[r * 128 + k + 3] * Wg[(k + 3) * 128 + c];
        }
        Wc[idx] = (s0 + s1) + (s2 + s3);
    } else if (threadIdx.x < 128) {
        int c = threadIdx.x;
        float s = 0.f;
#pragma unroll 8
        for (int k = 0; k < 128; k++) s += bp[k] * Wg[k * 128 + c];
        bc[c] = s;
    }
}

// ---------------- GEMM half2 out + fused attention coefficients ---------------
#define AT_LD 132
__global__ __launch_bounds__(256, 2) void gemm128h(const float* __restrict__ A,
                                                   const float* __restrict__ W,
                                                   const float* __restrict__ bias,
                                                   const float* __restrict__ a_src,
                                                   const float* __restrict__ a_dst,
                                                   __half2* __restrict__ C,
                                                   float* __restrict__ esrc,
                                                   float* __restrict__ edst, int N) {
    extern __shared__ float sm[];
    float* Ws = sm;                 // 128*128
    float* At = sm + 16384;         // 64*AT_LD
    const int t = threadIdx.x;
    const int row0 = blockIdx.x * 128;

    const float4* Wg = (const float4*)W;
    float4* Wsv = (float4*)Ws;
#pragma unroll
    for (int i = 0; i < 16; i++) Wsv[t + i * 256] = Wg[t + i * 256];

    const int w = t >> 5, lane = t & 31;
    const int rowb = (w >> 1) * 32;
    const int colb = (w & 1) * 64;
    const int rg = lane >> 3, cg = lane & 7;
    const int r8 = rowb + rg * 8;
    const int c8 = colb + cg * 8;

    unsigned long long acc[4][8];
#pragma unroll
    for (int i = 0; i < 4; i++)
#pragma unroll
        for (int j = 0; j < 8; j++) acc[i][j] = 0ull;

#pragma unroll
    for (int half = 0; half < 2; half++) {
        __syncthreads();
#pragma unroll
        for (int i = 0; i < 8; i++) {
            int idx = t + i * 256;
            int r  = idx >> 4;
            int k4 = idx & 15;
            float4 v = make_float4(0.f, 0.f, 0.f, 0.f);
            if (row0 + r < N)
                v = *(const float4*)(A + (size_t)(row0 + r) * 128 + half * 64 + k4 * 4);
            At[(k4 * 4 + 0) * AT_LD + r] = v.x;
            At[(k4 * 4 + 1) * AT_LD + r] = v.y;
            At[(k4 * 4 + 2) * AT_LD + r] = v.z;
            At[(k4 * 4 + 3) * AT_LD + r] = v.w;
        }
        __syncthreads();

#pragma unroll 4
        for (int k = 0; k < 64; k++) {
            ulonglong2 a01 = *(const ulonglong2*)(At + k * AT_LD + r8);
            ulonglong2 a23 = *(const ulonglong2*)(At + k * AT_LD + r8 + 4);
            float4 w0 = *(const float4*)(Ws + (half * 64 + k) * 128 + c8);
            float4 w1 = *(const float4*)(Ws + (half * 64 + k) * 128 + c8 + 4);
            unsigned long long ap[4] = {a01.x, a01.y, a23.x, a23.y};
            unsigned long long wp[8] = {pk2(w0.x, w0.x), pk2(w0.y, w0.y),
                                        pk2(w0.z, w0.z), pk2(w0.w, w0.w),
                                        pk2(w1.x, w1.x), pk2(w1.y, w1.y),
                                        pk2(w1.z, w1.z), pk2(w1.w, w1.w)};
#pragma unroll
            for (int i = 0; i < 4; i++)
#pragma unroll
                for (int j = 0; j < 8; j++) fma2(acc[i][j], ap[i], wp[j]);
        }
    }

    float4 b0 = *(const float4*)(bias + c8);
    float4 b1 = *(const float4*)(bias + c8 + 4);
    float bb[8] = {b0.x, b0.y, b0.z, b0.w, b1.x, b1.y, b1.z, b1.w};
    float4 as0 = *(const float4*)(a_src + c8);
    float4 as1 = *(const float4*)(a_src + c8 + 4);
    float4 ad0 = *(const float4*)(a_dst + c8);
    float4 ad1 = *(const float4*)(a_dst + c8 + 4);
    float sa8[8] = {as0.x, as0.y, as0.z, as0.w, as1.x, as1.y, as1.z, as1.w};
    float sd8[8] = {ad0.x, ad0.y, ad0.z, ad0.w, ad1.x, ad1.y, ad1.z, ad1.w};
    const int head = c8 >> 5;

#pragma unroll
    for (int i = 0; i < 4; i++) {
#pragma unroll
        for (int hr = 0; hr < 2; hr++) {
            int r = r8 + 2 * i + hr;
            bool ok = (row0 + r < N);
            float v[8];
#pragma unroll
            for (int j = 0; j < 8; j++) {
                float2 p = upk(acc[i][j]);
                v[j] = (hr ? p.y : p.x) + bb[j];
            }
            if (ok) {
                __half2 p0 = __float22half2_rn(make_float2(v[0], v[1]));
                __half2 p1 = __float22half2_rn(make_float2(v[2], v[3]));
                __half2 p2 = __float22half2_rn(make_float2(v[4], v[5]));
                __half2 p3 = __float22half2_rn(make_float2(v[6], v[7]));
                uint4 u;
                u.x = *(unsigned*)&p0; u.y = *(unsigned*)&p1;
                u.z = *(unsigned*)&p2; u.w = *(unsigned*)&p3;
                *(uint4*)(C + (size_t)(row0 + r) * 64 + c8 / 2) = u;
            }
            float ps = 0.f, pd = 0.f;
#pragma unroll
            for (int j = 0; j < 8; j++) { ps += v[j] * sa8[j]; pd += v[j] * sd8[j]; }
            ps += __shfl_xor_sync(0xFFFFFFFFu, ps, 1);
            pd += __shfl_xor_sync(0xFFFFFFFFu, pd, 1);
            ps += __shfl_xor_sync(0xFFFFFFFFu, ps, 2);
            pd += __shfl_xor_sync(0xFFFFFFFFu, pd, 2);
            if (ok && (lane & 3) == 0) {
                esrc[(row0 + r) * 4 + head] = ps;
                edst[(row0 + r) * 4 + head] = pd;
            }
        }
    }
}

// ---------------- CSR build ---------------------------------------------------
// hist with slot recording: pos[e] = slot of edge e within its dst bucket
__global__ void hist_pos(const int* __restrict__ ei, int* __restrict__ deg,
                         int* __restrict__ pos, int E) {
    int base = (blockIdx.x * blockDim.x + threadIdx.x) * 4;
    if (base >= E) return;
    if (base + 4 <= E) {
        int4 d = *(const int4*)(ei + E + base);
        int p0 = atomicAdd(deg + d.x, 1);
        int p1 = atomicAdd(deg + d.y, 1);
        int p2 = atomicAdd(deg + d.z, 1);
        int p3 = atomicAdd(deg + d.w, 1);
        *(int4*)(pos + base) = make_int4(p0, p1, p2, p3);
    } else {
        for (int e = base; e < E; e++) pos[e] = atomicAdd(deg + ei[E + e], 1);
    }
}

// single-pass exclusive scan with decoupled lookback (<=64 blocks, all resident)
__global__ __launch_bounds__(256) void scan_fused(const int* __restrict__ deg,
                                                  int* __restrict__ off,
                                                  volatile int* __restrict__ flags,
                                                  int* __restrict__ aggs,
                                                  int N, int E) {
    __shared__ int sc[256];
    __shared__ int s_pred[64];
    __shared__ int s_add;
    int t = threadIdx.x, bid = blockIdx.x;
    int base = bid * 1024 + t * 4;
    int v[4];
#pragma unroll
    for (int j = 0; j < 4; j++) v[j] = (base + j < N) ? deg[base + j] : 0;
    int s = v[0] + v[1] + v[2] + v[3];
    sc[t] = s;
    __syncthreads();
    for (int d = 1; d < 256; d <<= 1) {
        int val = (t >= d) ? sc[t - d] : 0;
        __syncthreads();
        sc[t] += val;
        __syncthreads();
    }
    if (t == 0) {
        aggs[bid] = sc[255];
        __threadfence();
        flags[bid] = 1;
    }
    if (t < 64) {
        int p = 0;
        if (t < bid) {
            while (flags[t] == 0) { }
            p = aggs[t];
        }
        s_pred[t] = p;
    }
    __syncthreads();
    if (t == 0) {
        int a = 0;
#pragma unroll 8
        for (int i = 0; i < 64; i++) a += s_pred[i];
        s_add = a;
    }
    __syncthreads();
    int add = s_add;
    int run = add + ((t == 0) ? 0 : sc[t - 1]);
#pragma unroll
    for (int j = 0; j < 4; j++) {
        if (base + j < N) off[base + j] = run;
        run += v[j];
    }
    if (bid == 0 && t == 0) off[N] = E;
}

// atomic-free placement: srcs[off[d] + pos[e]] = s
__global__ void place_kernel(const int* __restrict__ ei, const int* __restrict__ off,
                             const int* __restrict__ pos, int* __restrict__ srcs, int E) {
    int base = (blockIdx.x * blockDim.x + threadIdx.x) * 4;
    if (base >= E) return;
    if (base + 4 <= E) {
        int4 s = *(const int4*)(ei + base);
        int4 d = *(const int4*)(ei + E + base);
        int4 p = *(const int4*)(pos + base);
        int o0 = off[d.x], o1 = off[d.y], o2 = off[d.z], o3 = off[d.w];
        srcs[o0 + p.x] = s.x;
        srcs[o1 + p.y] = s.y;
        srcs[o2 + p.z] = s.z;
        srcs[o3 + p.w] = s.w;
    } else {
        for (int e = base; e < E; e++)
            srcs[off[ei[E + e]] + pos[e]] = ei[e];
    }
}

// ---------------- fused softmax + aggregate + pool (warp per dst node) --------
// R13-proven: smem alpha cache + block-level pooled reduction (1 RED/block).
#define CAP 64
__global__ __launch_bounds__(256, 6) void agg_fused(const int* __restrict__ off,
                                                    const int* __restrict__ srcs,
                                                    const float* __restrict__ esrc,
                                                    const float* __restrict__ edst,
                                                    const __half2* __restrict__ hh,
                                                    const int* __restrict__ batch,
                                                    float* __restrict__ pooled, int N) {
    __shared__ int    sh_src[8][CAP];
    __shared__ float  sh_al[8][4][CAP + 1];
    __shared__ float4 sacc[8][32];
    __shared__ int    sg[8];
    int wi = threadIdx.x >> 5;
    int w = (blockIdx.x * blockDim.x + threadIdx.x) >> 5;
    int lane = threadIdx.x & 31;

    float4 total = make_float4(0.f, 0.f, 0.f, 0.f);
    int g = -1;

    if (w < N) {
        g = batch[w];
        int beg = off[w], end = off[w + 1];
        int deg = end - beg;
        if (deg > 0) {
            float4 b = *(const float4*)(edst + w * 4);

            float4 dsum = make_float4(0.f, 0.f, 0.f, 0.f);
            for (int i = lane; i < deg; i += 32) {
                int s = srcs[beg + i];
                float4 a = *(const float4*)(esrc + s * 4);
                float ex0 = __expf(lrelu(a.x + b.x));
                float ex1 = __expf(lrelu(a.y + b.y));
                float ex2 = __expf(lrelu(a.z + b.z));
                float ex3 = __expf(lrelu(a.w + b.w));
                if (i < CAP) {
                    sh_src[wi][i] = s;
                    sh_al[wi][0][i] = ex0;
                    sh_al[wi][1][i] = ex1;
                    sh_al[wi][2][i] = ex2;
                    sh_al[wi][3][i] = ex3;
                }
                dsum.x += ex0; dsum.y += ex1; dsum.z += ex2; dsum.w += ex3;
            }
#pragma unroll
            for (int d = 16; d; d >>= 1) {
                dsum.x += __shfl_xor_sync(0xFFFFFFFFu, dsum.x, d);
                dsum.y += __shfl_xor_sync(0xFFFFFFFFu, dsum.y, d);
                dsum.z += __shfl_xor_sync(0xFFFFFFFFu, dsum.z, d);
                dsum.w += __shfl_xor_sync(0xFFFFFFFFu, dsum.w, d);
            }
            __syncwarp();

            int h = lane >> 3;
            float bh  = (h == 0) ? b.x : (h == 1) ? b.y : (h == 2) ? b.z : b.w;
            float dh  = (h == 0) ? dsum.x : (h == 1) ? dsum.y : (h == 2) ? dsum.z : dsum.w;
            float inv = 1.0f / dh;

            const float* alp = sh_al[wi][h];
            const int*   sp  = sh_src[wi];
            const __half2* hbase = hh + lane * 2;

            float4 acc0 = make_float4(0.f, 0.f, 0.f, 0.f);
            float4 acc1 = make_float4(0.f, 0.f, 0.f, 0.f);
            int nfast = (deg < CAP) ? deg : CAP;
            int i = 0;
            for (; i + 1 < nfast; i += 2) {
                int s0 = sp[i], s1 = sp[i + 1];
                float al0 = alp[i] * inv, al1 = alp[i + 1] * inv;
                uint2 r0 = *(const uint2*)(hbase + (size_t)s0 * 64);
                uint2 r1 = *(const uint2*)(hbase + (size_t)s1 * 64);
                float2 a0 = __half22float2(*(__half2*)&r0.x);
                float2 b0v = __half22float2(*(__half2*)&r0.y);
                float2 a1 = __half22float2(*(__half2*)&r1.x);
                float2 b1v = __half22float2(*(__half2*)&r1.y);
                acc0.x += al0 * a0.x;  acc0.y += al0 * a0.y;
                acc0.z += al0 * b0v.x; acc0.w += al0 * b0v.y;
                acc1.x += al1 * a1.x;  acc1.y += al1 * a1.y;
                acc1.z += al1 * b1v.x; acc1.w += al1 * b1v.y;
            }
            for (; i < nfast; i++) {
                int s = sp[i];
                float alpha = alp[i] * inv;
                uint2 r = *(const uint2*)(hbase + (size_t)s * 64);
                float2 v0 = __half22float2(*(__half2*)&r.x);
                float2 v1 = __half22float2(*(__half2*)&r.y);
                acc0.x += alpha * v0.x; acc0.y += alpha * v0.y;
                acc0.z += alpha * v1.x; acc0.w += alpha * v1.y;
            }
            for (int j = CAP; j < deg; j++) {
                int s = srcs[beg + j];
                float alpha = __expf(lrelu(esrc[s * 4 + h] + bh)) * inv;
                uint2 r = *(const uint2*)(hbase + (size_t)s * 64);
                float2 v0 = __half22float2(*(__half2*)&r.x);
                float2 v1 = __half22float2(*(__half2*)&r.y);
                acc0.x += alpha * v0.x; acc0.y += alpha * v0.y;
                acc0.z += alpha * v1.x; acc0.w += alpha * v1.y;
            }
            total = make_float4(acc0.x + acc1.x, acc0.y + acc1.y,
                                acc0.z + acc1.z, acc0.w + acc1.w);
        }
    }

    sacc[wi][lane] = total;
    if (lane == 0) sg[wi] = g;
    __syncthreads();
    int myg = sg[wi];
    bool leader = (myg >= 0);
#pragma unroll
    for (int j = 0; j < 8; j++)
        if (j < wi && sg[j] == myg) leader = false;
    if (leader) {
        float4 tot = sacc[wi][lane];
#pragma unroll
        for (int j = 0; j < 8; j++) {
            if (j > wi && sg[j] == myg) {
                float4 o = sacc[j][lane];
                tot.x += o.x; tot.y += o.y; tot.z += o.z; tot.w += o.w;
            }
        }
        red_add_v4(pooled + myg * 128 + lane * 4, tot);
    }
}

// ---------------- classifier: warp per graph; counts via bsearch on batch -----
__global__ __launch_bounds__(1024) void classifier(const float* __restrict__ pooled,
                                                   const int* __restrict__ batch,
                                                   const float* __restrict__ Wc1,
                                                   const float* __restrict__ bc1,
                                                   const float* __restrict__ Wc2,
                                                   const float* __restrict__ bc2,
                                                   float* __restrict__ outp, int N) {
    __shared__ float sW1[128 * 64];
    __shared__ float srow[32][128];
    int t = threadIdx.x;
    int warp = t >> 5, lane = t & 31;
    int g = blockIdx.x * 32 + warp;
    for (int i = t; i < 8192; i += 1024) sW1[i] = Wc1[i];

    int cnt;
    if (lane == 0) {
        int lo = 0, hi = N;
        while (lo < hi) { int m = (lo + hi) >> 1; if (batch[m] < g) lo = m + 1; else hi = m; }
        int lb = lo;
        lo = 0; hi = N;
        while (lo < hi) { int m = (lo + hi) >> 1; if (batch[m] < g + 1) lo = m + 1; else hi = m; }
        cnt = lo - lb;
    }
    cnt = __shfl_sync(0xFFFFFFFFu, cnt, 0);
    float inv = 1.0f / fmaxf((float)cnt, 1.0f);

    float4 rv = *(const float4*)(pooled + g * 128 + lane * 4);
    srow[warp][lane * 4 + 0] = rv.x * inv;
    srow[warp][lane * 4 + 1] = rv.y * inv;
    srow[warp][lane * 4 + 2] = rv.z * inv;
    srow[warp][lane * 4 + 3] = rv.w * inv;
    __syncthreads();

    int j0 = lane * 2;
    float s0 = bc1[j0], s1 = bc1[j0 + 1];
#pragma unroll 8
    for (int k = 0; k < 128; k++) {
        float r = srow[warp][k];
        s0 += r * sW1[k * 64 + j0];
        s1 += r * sW1[k * 64 + j0 + 1];
    }
    s0 = fmaxf(s0, 0.f);
    s1 = fmaxf(s1, 0.f);
    float o0 = s0 * Wc2[j0 * 2]     + s1 * Wc2[(j0 + 1) * 2];
    float o1 = s0 * Wc2[j0 * 2 + 1] + s1 * Wc2[(j0 + 1) * 2 + 1];
#pragma unroll
    for (int d = 16; d; d >>= 1) {
        o0 += __shfl_xor_sync(0xFFFFFFFFu, o0, d);
        o1 += __shfl_xor_sync(0xFFFFFFFFu, o1, d);
    }
    if (lane == 0) {
        outp[g * 2 + 0] = o0 + bc2[0];
        outp[g * 2 + 1] = o1 + bc2[1];
    }
}

// ---------------- launch ------------------------------------------------------
extern "C" void kernel_launch(void* const* d_in, const int* in_sizes, int n_in,
                              void* d_out, int out_size) {
    const float* x      = (const float*)d_in[0];
    const int*   ei     = (const int*)d_in[1];
    const int*   batch  = (const int*)d_in[2];
    const float* W_proj = (const float*)d_in[3];
    const float* b_proj = (const float*)d_in[4];
    const float* W_gat  = (const float*)d_in[5];
    const float* a_src  = (const float*)d_in[6];
    const float* a_dst  = (const float*)d_in[7];
    const float* Wc1    = (const float*)d_in[8];
    const float* bc1    = (const float*)d_in[9];
    const float* Wc2    = (const float*)d_in[10];
    const float* bc2    = (const float*)d_in[11];

    int N = in_sizes[0] / 128;
    int E = in_sizes[1] / 2;

    __half2* p_hh;
    float *p_Wcomb, *p_bcomb, *p_esrc, *p_edst, *p_pooled;
    int *p_deg, *p_off, *p_pos, *p_srcs, *p_flag, *p_agg;
    cudaGetSymbolAddress((void**)&p_hh, g_hh);
    cudaGetSymbolAddress((void**)&p_Wcomb, g_Wcomb);
    cudaGetSymbolAddress((void**)&p_bcomb, g_bcomb);
    cudaGetSymbolAddress((void**)&p_esrc, g_esrc);
    cudaGetSymbolAddress((void**)&p_edst, g_edst);
    cudaGetSymbolAddress((void**)&p_deg, g_deg);
    cudaGetSymbolAddress((void**)&p_off, g_off);
    cudaGetSymbolAddress((void**)&p_pos, g_pos);
    cudaGetSymbolAddress((void**)&p_srcs, g_srcsort);
    cudaGetSymbolAddress((void**)&p_flag, g_flag);
    cudaGetSymbolAddress((void**)&p_agg, g_agg);
    cudaGetSymbolAddress((void**)&p_pooled, g_pooled);

    const int GEMM_SMEM = (16384 + 64 * AT_LD) * 4;
    cudaFuncSetAttribute(gemm128h, cudaFuncAttributeMaxDynamicSharedMemorySize, GEMM_SMEM);

    cudaStream_t s2;
    cudaEvent_t ev_fork, ev_join;
    cudaStreamCreateWithFlags(&s2, cudaStreamNonBlocking);
    cudaEventCreateWithFlags(&ev_fork, cudaEventDisableTiming);
    cudaEventCreateWithFlags(&ev_join, cudaEventDisableTiming);

    int nb = (N + 1023) / 1024;

    // ---- fork immediately: CSR path starts at t=0 on s2
    cudaEventRecord(ev_fork, 0);
    cudaStreamWaitEvent(s2, ev_fork, 0);
    cudaMemsetAsync(p_deg, 0, (size_t)N * sizeof(int), s2);
    cudaMemsetAsync(p_flag, 0, 64 * sizeof(int), s2);
    hist_pos<<<(E / 4 + 255) / 256, 256, 0, s2>>>(ei, p_deg, p_pos, E);
    scan_fused<<<nb, 256, 0, s2>>>(p_deg, p_off, p_flag, p_agg, N, E);
    place_kernel<<<(E / 4 + 255) / 256, 256, 0, s2>>>(ei, p_off, p_pos, p_srcs, E);
    cudaEventRecord(ev_join, s2);

    // ---- stream 0: pooled zero + Wcomb/bias, then hh GEMM (+attn coefs)
    init_wcomb<<<97, 256>>>(p_pooled, W_proj, W_gat, b_proj, p_Wcomb, p_bcomb);
    gemm128h<<<(N + 127) / 128, 256, GEMM_SMEM>>>(x, p_Wcomb, p_bcomb, a_src, a_dst,
                                                  p_hh, p_esrc, p_edst, N);

    // ---- join, aggregate, classify
    cudaStreamWaitEvent(0, ev_join, 0);
    agg_fused<<<(N * 32 + 255) / 256, 256>>>(p_off, p_srcs, p_esrc, p_edst,
                                             p_hh, batch, p_pooled, N);
    classifier<<<2, 1024>>>(p_pooled, batch, Wc1, bc1, Wc2, bc2, (float*)d_out, N);
}